// round 3
// baseline (speedup 1.0000x reference)
#include <cuda_runtime.h>
#include <cuda_bf16.h>

// IndRNN: proj = x @ W + b  (GEMM, M=B*T=32768, K=D=256, N=U=512)
//         h_t  = relu(proj_t + h_{t-1} * clip(u,0,1))  (scan over T, in-place on d_out)
//
// Inputs (metadata order): x [64,512,256] f32, h0 [64,512] f32, W [256,512] f32,
//                          u [512] f32, b [512] f32. Output [64,512,512] f32.

#define BATCH 64
#define TT    512
#define DD    256
#define UU    512
#define MM    (BATCH * TT)   // 32768

// ---------------- GEMM: proj = x @ W + bias, written into d_out ----------------
// Block tile 128(M) x 64(N), K-tile 16, 256 threads, 8x4 outputs per thread.
__global__ __launch_bounds__(256) void indrnn_gemm(
    const float* __restrict__ A,     // x  [M, 256]
    const float* __restrict__ Wm,    // W  [256, 512]
    const float* __restrict__ bias,  // b  [512]
    float* __restrict__ C)           // out [M, 512]
{
    __shared__ float As[16][132];    // transposed A tile [k][m], padded row
    __shared__ float Bs[16][64];     // B tile [k][n]

    const int tid = threadIdx.x;
    const int bm = blockIdx.y * 128;
    const int bn = blockIdx.x * 64;

    const int tx = tid & 15;         // N-dim thread coord (16) -> 4 cols each
    const int ty = tid >> 4;         // M-dim thread coord (16) -> 8 rows each

    // A-load mapping: float4 along K. 64 rows per load round, 2 rounds.
    const int a_row = tid >> 2;        // 0..63
    const int a_col = (tid & 3) << 2;  // 0,4,8,12
    // B-load mapping: one float4 per thread
    const int b_row = tid >> 4;        // 0..15 (k)
    const int b_col = (tid & 15) << 2; // 0..60 (n)

    float acc[8][4];
#pragma unroll
    for (int i = 0; i < 8; i++)
#pragma unroll
        for (int j = 0; j < 4; j++) acc[i][j] = 0.0f;

    for (int k0 = 0; k0 < DD; k0 += 16) {
        float4 av0 = *(const float4*)(A + (size_t)(bm + a_row)      * DD + k0 + a_col);
        float4 av1 = *(const float4*)(A + (size_t)(bm + a_row + 64) * DD + k0 + a_col);
        *(float4*)(&Bs[b_row][b_col]) =
            *(const float4*)(Wm + (size_t)(k0 + b_row) * UU + bn + b_col);

        As[a_col + 0][a_row] = av0.x;
        As[a_col + 1][a_row] = av0.y;
        As[a_col + 2][a_row] = av0.z;
        As[a_col + 3][a_row] = av0.w;
        As[a_col + 0][a_row + 64] = av1.x;
        As[a_col + 1][a_row + 64] = av1.y;
        As[a_col + 2][a_row + 64] = av1.z;
        As[a_col + 3][a_row + 64] = av1.w;
        __syncthreads();

#pragma unroll
        for (int k = 0; k < 16; k++) {
            float ar[8], br[4];
            *(float4*)(ar)     = *(const float4*)(&As[k][ty * 8]);
            *(float4*)(ar + 4) = *(const float4*)(&As[k][ty * 8 + 4]);
            *(float4*)(br)     = *(const float4*)(&Bs[k][tx * 4]);
#pragma unroll
            for (int i = 0; i < 8; i++)
#pragma unroll
                for (int j = 0; j < 4; j++)
                    acc[i][j] = fmaf(ar[i], br[j], acc[i][j]);
        }
        __syncthreads();
    }

    const float4 bv = *(const float4*)(bias + bn + tx * 4);
#pragma unroll
    for (int i = 0; i < 8; i++) {
        float4 o;
        o.x = acc[i][0] + bv.x;
        o.y = acc[i][1] + bv.y;
        o.z = acc[i][2] + bv.z;
        o.w = acc[i][3] + bv.w;
        *(float4*)(C + (size_t)(bm + ty * 8 + i) * UU + bn + tx * 4) = o;
    }
}

// ---------------- Scan: in-place over d_out, one thread per (b,u) lane ----------------
// Depth-4 software prefetch: loads for t+4..t+7 are issued before the dependent
// relu/FMA chain of t..t+3, so L2 latency overlaps the recurrence.
__global__ __launch_bounds__(256) void indrnn_scan(
    const float* __restrict__ h0,
    const float* __restrict__ u,
    float* __restrict__ out)
{
    const int idx = blockIdx.x * blockDim.x + threadIdx.x;  // 0 .. B*U-1
    const int uu = idx & (UU - 1);
    const int bb = idx >> 9;  // /512

    const float uc = fminf(fmaxf(u[uu], 0.0f), 1.0f);
    float h = h0[bb * UU + uu];

    float* p = out + (size_t)bb * TT * UU + uu;

    float p0 = p[0 * UU];
    float p1 = p[1 * UU];
    float p2 = p[2 * UU];
    float p3 = p[3 * UU];

    for (int t = 0; t < TT; t += 4) {
        float n0 = 0.f, n1 = 0.f, n2 = 0.f, n3 = 0.f;
        if (t + 4 < TT) {
            n0 = p[(size_t)(t + 4) * UU];
            n1 = p[(size_t)(t + 5) * UU];
            n2 = p[(size_t)(t + 6) * UU];
            n3 = p[(size_t)(t + 7) * UU];
        }
        h = fmaxf(fmaf(h, uc, p0), 0.0f); p[(size_t)(t + 0) * UU] = h;
        h = fmaxf(fmaf(h, uc, p1), 0.0f); p[(size_t)(t + 1) * UU] = h;
        h = fmaxf(fmaf(h, uc, p2), 0.0f); p[(size_t)(t + 2) * UU] = h;
        h = fmaxf(fmaf(h, uc, p3), 0.0f); p[(size_t)(t + 3) * UU] = h;
        p0 = n0; p1 = n1; p2 = n2; p3 = n3;
    }
}

extern "C" void kernel_launch(void* const* d_in, const int* in_sizes, int n_in,
                              void* d_out, int out_size)
{
    const float* x  = (const float*)d_in[0];  // [64,512,256]
    const float* h0 = (const float*)d_in[1];  // [64,512]
    const float* W  = (const float*)d_in[2];  // [256,512]
    const float* u  = (const float*)d_in[3];  // [512]
    const float* b  = (const float*)d_in[4];  // [512]
    float* out = (float*)d_out;               // [64,512,512]

    dim3 grid(UU / 64, MM / 128);             // (8, 256)
    indrnn_gemm<<<grid, 256>>>(x, W, b, out);

    indrnn_scan<<<(BATCH * UU) / 256, 256>>>(h0, u, out);
}

// round 7
// speedup vs baseline: 1.6404x; 1.6404x over previous
#include <cuda_runtime.h>
#include <cuda_bf16.h>
#include <cstdint>

// IndRNN on GB300 (compute_103 PTX target -> no tcgen05; use mma.sync fallback HMMA):
//   proj = x @ W + b  via bf16 hi/lo 3-term split (x_hi*W_hi + x_hi*W_lo + x_lo*W_hi)
//   h_t  = relu(proj_t + h_{t-1} * clip(u,0,1))  scan in-place on d_out
//
// Inputs: x [64,512,256] f32, h0 [64,512] f32, W [256,512] f32, u [512] f32, b [512] f32.
// Output [64,512,512] f32.

#define BATCH 64
#define TT    512
#define DD    256
#define UU    512
#define MM    (BATCH * TT)      // 32768
#define K2    512               // [hi(256) | lo(256)]

// ---------------- device scratch ----------------
__device__ __align__(16) __nv_bfloat16 g_A2[(size_t)MM * K2];   // 32 MB  [m][hi|lo]
__device__ __align__(16) __nv_bfloat16 g_B2t[(size_t)UU * K2];  // 512 KB [n][hi|lo] (W^T)

// ---------------- PTX helpers (all baseline <= sm_80, safe for compute_103) ----------------
__device__ __forceinline__ uint32_t smem_u32(const void* p) {
    uint32_t a;
    asm("{ .reg .u64 t; cvta.to.shared.u64 t, %1; cvt.u32.u64 %0, t; }" : "=r"(a) : "l"(p));
    return a;
}
#define CP16(dst, src) \
    asm volatile("cp.async.cg.shared.global [%0], [%1], 16;" :: "r"(dst), "l"(src) : "memory")
#define CP_COMMIT() asm volatile("cp.async.commit_group;" ::: "memory")
#define CP_WAIT1()  asm volatile("cp.async.wait_group 1;" ::: "memory")
#define CP_WAIT0()  asm volatile("cp.async.wait_group 0;" ::: "memory")

#define LDSM_X4(r0, r1, r2, r3, addr) \
    asm volatile("ldmatrix.sync.aligned.m8n8.x4.shared.b16 {%0,%1,%2,%3}, [%4];" \
        : "=r"(r0), "=r"(r1), "=r"(r2), "=r"(r3) : "r"(addr))
#define LDSM_X2(r0, r1, addr) \
    asm volatile("ldmatrix.sync.aligned.m8n8.x2.shared.b16 {%0,%1}, [%2];" \
        : "=r"(r0), "=r"(r1) : "r"(addr))

#define MMA_BF16(d, a, b0, b1) \
    asm volatile("mma.sync.aligned.m16n8k16.row.col.f32.bf16.bf16.f32 " \
        "{%0,%1,%2,%3}, {%4,%5,%6,%7}, {%8,%9}, {%0,%1,%2,%3};" \
        : "+f"((d)[0]), "+f"((d)[1]), "+f"((d)[2]), "+f"((d)[3]) \
        : "r"((a)[0]), "r"((a)[1]), "r"((a)[2]), "r"((a)[3]), "r"(b0), "r"(b1))

// ---------------- prep: split x into bf16 hi|lo ----------------
__global__ __launch_bounds__(256) void convert_x(const float4* __restrict__ x4) {
    int idx = blockIdx.x * blockDim.x + threadIdx.x;     // MM*DD/4 = 2097152
    int m  = idx >> 6;                                    // 64 float4 per row
    int k4 = (idx & 63) << 2;
    float4 v = x4[idx];
    __nv_bfloat162 h01 = __floats2bfloat162_rn(v.x, v.y);
    __nv_bfloat162 h23 = __floats2bfloat162_rn(v.z, v.w);
    float lx = v.x - __low2float(h01);
    float ly = v.y - __high2float(h01);
    float lz = v.z - __low2float(h23);
    float lw = v.w - __high2float(h23);
    __nv_bfloat162 l01 = __floats2bfloat162_rn(lx, ly);
    __nv_bfloat162 l23 = __floats2bfloat162_rn(lz, lw);
    __nv_bfloat162* dh = reinterpret_cast<__nv_bfloat162*>(g_A2 + (size_t)m * K2 + k4);
    dh[0] = h01; dh[1] = h23;
    __nv_bfloat162* dl = reinterpret_cast<__nv_bfloat162*>(g_A2 + (size_t)m * K2 + DD + k4);
    dl[0] = l01; dl[1] = l23;
}

// ---------------- prep: split + transpose W ----------------
__global__ __launch_bounds__(256) void convert_w(const float* __restrict__ W) {
    int idx = blockIdx.x * blockDim.x + threadIdx.x;     // 131072
    int n = idx & (UU - 1);
    int k = idx >> 9;
    float w = W[(size_t)k * UU + n];
    __nv_bfloat16 h = __float2bfloat16(w);
    float l = w - __bfloat162float(h);
    g_B2t[(size_t)n * K2 + k]      = h;
    g_B2t[(size_t)n * K2 + DD + k] = __float2bfloat16(l);
}

// ---------------- GEMM via mma.sync (fallback HMMA) ----------------
// CTA tile 128(M) x 128(N), K-chunk 32, double-buffered cp.async.
// 8 warps: warp_m = wid&3 (32 rows), warp_n = wid>>2 (64 cols). Warp tile 32x64.
// smem rows padded to 80B -> ldmatrix conflict-free (r*80 mod 128 covers 8 groups).
#define ROWB     80
#define BUF_SZ   (128 * ROWB)          // 10240 B
#define STAGE_SZ (4 * BUF_SZ)          // Ahi, Alo, Bhi, Blo = 40960 B
#define SM_TOTAL (2 * STAGE_SZ)        // 81920 B

__device__ __forceinline__ void load_chunk(uint32_t stage_base, int bm, int bn, int k0, int tid) {
    const char* gA = reinterpret_cast<const char*>(g_A2);
    const char* gB = reinterpret_cast<const char*>(g_B2t);
#pragma unroll
    for (int r = 0; r < 2; r++) {
        int idx = tid + r * 256;          // 0..511
        int row = idx >> 2;
        int seg = (idx & 3) << 4;         // 0,16,32,48
        uint32_t so = stage_base + row * ROWB + seg;
        const char* srcA = gA + (size_t)(bm + row) * 1024 + k0 * 2 + seg;
        const char* srcB = gB + (size_t)(bn + row) * 1024 + k0 * 2 + seg;
        CP16(so,              srcA);        // A hi
        CP16(so + BUF_SZ,     srcA + 512);  // A lo (+256 bf16)
        CP16(so + 2 * BUF_SZ, srcB);        // B hi
        CP16(so + 3 * BUF_SZ, srcB + 512);  // B lo
    }
}

__global__ __launch_bounds__(256, 2) void indrnn_gemm_mma(
    const float* __restrict__ bias, float* __restrict__ C)
{
    extern __shared__ char smem[];
    const uint32_t sbase = smem_u32(smem);
    const int tid  = threadIdx.x;
    const int wid  = tid >> 5;
    const int lane = tid & 31;
    const int bm   = blockIdx.y * 128;
    const int bn   = blockIdx.x * 128;
    const int wm   = (wid & 3) * 32;     // warp m offset
    const int wn   = (wid >> 2) * 64;    // warp n offset

    float acc[2][8][4];
#pragma unroll
    for (int mt = 0; mt < 2; mt++)
#pragma unroll
        for (int nt = 0; nt < 8; nt++)
#pragma unroll
            for (int i = 0; i < 4; i++) acc[mt][nt][i] = 0.0f;

    // prologue: chunks 0,1 into stages 0,1
    load_chunk(sbase,            bm, bn, 0,  tid); CP_COMMIT();
    load_chunk(sbase + STAGE_SZ, bm, bn, 32, tid); CP_COMMIT();

    // per-lane ldmatrix address components
    const uint32_t a_row = wm + (lane & 15);             // + mt*16
    const uint32_t a_col = (lane >> 4) * 16;             // + k16*32
    const uint32_t b_row = wn + (lane & 7);              // + nt*8
    const uint32_t b_col = ((lane >> 3) & 1) * 16;       // + k16*32

    for (int c = 0; c < 8; c++) {
        if (c < 7) { CP_WAIT1(); } else { CP_WAIT0(); }
        __syncthreads();

        const uint32_t st = sbase + (c & 1) * STAGE_SZ;
        const uint32_t aHi = st;
        const uint32_t aLo = st + BUF_SZ;
        const uint32_t bHi = st + 2 * BUF_SZ;
        const uint32_t bLo = st + 3 * BUF_SZ;

        // A fragments (cached across all 8 n-tiles)
        uint32_t ah[2][2][4], al[2][2][4];   // [k16][mt][4]
#pragma unroll
        for (int k16 = 0; k16 < 2; k16++)
#pragma unroll
            for (int mt = 0; mt < 2; mt++) {
                uint32_t off = (a_row + mt * 16) * ROWB + k16 * 32 + a_col;
                LDSM_X4(ah[k16][mt][0], ah[k16][mt][1], ah[k16][mt][2], ah[k16][mt][3], aHi + off);
                LDSM_X4(al[k16][mt][0], al[k16][mt][1], al[k16][mt][2], al[k16][mt][3], aLo + off);
            }

#pragma unroll
        for (int nt = 0; nt < 8; nt++) {
            uint32_t boff = (b_row + nt * 8) * ROWB + b_col;
            uint32_t bh[4], bl[4];
            LDSM_X2(bh[0], bh[1], bHi + boff);
            LDSM_X2(bh[2], bh[3], bHi + boff + 32);
            LDSM_X2(bl[0], bl[1], bLo + boff);
            LDSM_X2(bl[2], bl[3], bLo + boff + 32);
#pragma unroll
            for (int k16 = 0; k16 < 2; k16++) {
                // hi*hi
                MMA_BF16(acc[0][nt], ah[k16][0], bh[2 * k16], bh[2 * k16 + 1]);
                MMA_BF16(acc[1][nt], ah[k16][1], bh[2 * k16], bh[2 * k16 + 1]);
                // lo*hi
                MMA_BF16(acc[0][nt], al[k16][0], bh[2 * k16], bh[2 * k16 + 1]);
                MMA_BF16(acc[1][nt], al[k16][1], bh[2 * k16], bh[2 * k16 + 1]);
                // hi*lo
                MMA_BF16(acc[0][nt], ah[k16][0], bl[2 * k16], bl[2 * k16 + 1]);
                MMA_BF16(acc[1][nt], ah[k16][1], bl[2 * k16], bl[2 * k16 + 1]);
            }
        }

        __syncthreads();   // done reading this stage before overwriting it
        if (c + 2 < 8) { load_chunk(st, bm, bn, (c + 2) * 32, tid); CP_COMMIT(); }
    }

    // epilogue: c-frag thread t holds (m = t/4 [+8], n = (t%4)*2 [+1])
    const int m0   = bm + wm + (lane >> 2);
    const int col0 = bn + wn + (lane & 3) * 2;
#pragma unroll
    for (int mt = 0; mt < 2; mt++) {
#pragma unroll
        for (int nt = 0; nt < 8; nt++) {
            const int r = m0 + mt * 16;
            const int cc = col0 + nt * 8;
            const float2 bv = *reinterpret_cast<const float2*>(bias + cc);
            float2 o0, o1;
            o0.x = acc[mt][nt][0] + bv.x;
            o0.y = acc[mt][nt][1] + bv.y;
            o1.x = acc[mt][nt][2] + bv.x;
            o1.y = acc[mt][nt][3] + bv.y;
            *reinterpret_cast<float2*>(C + (size_t)r * UU + cc)       = o0;
            *reinterpret_cast<float2*>(C + (size_t)(r + 8) * UU + cc) = o1;
        }
    }
}

// ---------------- scan: deep prefetch (16 outstanding), 128-thread blocks ----------------
__global__ __launch_bounds__(128) void indrnn_scan(
    const float* __restrict__ h0,
    const float* __restrict__ u,
    float* __restrict__ out)
{
    const int idx = blockIdx.x * 128 + threadIdx.x;   // 0 .. B*U-1
    const int uu = idx & (UU - 1);
    const int bb = idx >> 9;

    const float uc = fminf(fmaxf(u[uu], 0.0f), 1.0f);
    float h = h0[bb * UU + uu];
    float* p = out + (size_t)bb * TT * UU + uu;

    float buf[16];
#pragma unroll
    for (int i = 0; i < 16; i++) buf[i] = p[(size_t)i * UU];

#pragma unroll 1
    for (int t = 0; t < TT; t += 16) {
        float nb[16];
        const bool more = (t + 16) < TT;
#pragma unroll
        for (int i = 0; i < 16; i++) nb[i] = more ? p[(size_t)(t + 16 + i) * UU] : 0.0f;
#pragma unroll
        for (int i = 0; i < 16; i++) {
            h = fmaxf(fmaf(h, uc, buf[i]), 0.0f);
            p[(size_t)(t + i) * UU] = h;
        }
#pragma unroll
        for (int i = 0; i < 16; i++) buf[i] = nb[i];
    }
}

extern "C" void kernel_launch(void* const* d_in, const int* in_sizes, int n_in,
                              void* d_out, int out_size)
{
    const float* x  = (const float*)d_in[0];
    const float* h0 = (const float*)d_in[1];
    const float* W  = (const float*)d_in[2];
    const float* u  = (const float*)d_in[3];
    const float* b  = (const float*)d_in[4];
    float* out = (float*)d_out;

    cudaFuncSetAttribute(indrnn_gemm_mma, cudaFuncAttributeMaxDynamicSharedMemorySize, SM_TOTAL);

    convert_x<<<(MM * DD / 4) / 256, 256>>>(reinterpret_cast<const float4*>(x));
    convert_w<<<(DD * UU) / 256, 256>>>(W);

    dim3 grid(UU / 128, MM / 128);   // (4, 256)
    indrnn_gemm_mma<<<grid, 256, SM_TOTAL>>>(b, out);

    indrnn_scan<<<(BATCH * UU) / 128, 128>>>(h0, u, out);
}

// round 9
// speedup vs baseline: 1.9871x; 1.2113x over previous
#include <cuda_runtime.h>
#include <cuda_bf16.h>
#include <cstdint>

// IndRNN on GB300 (compute_103 target -> mma.sync fallback HMMA, no tcgen05):
//   proj = x @ W + b  via bf16 hi/lo 3-term split (x_hi*W_hi + x_lo*W_hi + x_hi*W_lo)
//   h_t  = relu(proj_t + h_{t-1} * clip(u,0,1))  scan in-place on d_out
//
// Inputs: x [64,512,256] f32, h0 [64,512] f32, W [256,512] f32, u [512] f32, b [512] f32.
// Output [64,512,512] f32.

#define BATCH 64
#define TT    512
#define DD    256
#define UU    512
#define MM    (BATCH * TT)      // 32768
#define K2    512               // [hi(256) | lo(256)]

// ---------------- device scratch ----------------
__device__ __align__(16) __nv_bfloat16 g_A2[(size_t)MM * K2];   // 32 MB  [m][hi|lo]
__device__ __align__(16) __nv_bfloat16 g_B2t[(size_t)UU * K2];  // 512 KB [n][hi|lo] (W^T)

// ---------------- PTX helpers (baseline <= sm_80, safe for compute_103) ----------------
__device__ __forceinline__ uint32_t smem_u32(const void* p) {
    uint32_t a;
    asm("{ .reg .u64 t; cvta.to.shared.u64 t, %1; cvt.u32.u64 %0, t; }" : "=r"(a) : "l"(p));
    return a;
}
#define CP16(dst, src) \
    asm volatile("cp.async.cg.shared.global [%0], [%1], 16;" :: "r"(dst), "l"(src) : "memory")
#define CP_COMMIT() asm volatile("cp.async.commit_group;" ::: "memory")
#define CP_WAITN(n) asm volatile("cp.async.wait_group %0;" :: "n"(n) : "memory")

#define LDSM_X4(r0, r1, r2, r3, addr) \
    asm volatile("ldmatrix.sync.aligned.m8n8.x4.shared.b16 {%0,%1,%2,%3}, [%4];" \
        : "=r"(r0), "=r"(r1), "=r"(r2), "=r"(r3) : "r"(addr))

#define MMA_BF16(d, a, b0, b1) \
    asm volatile("mma.sync.aligned.m16n8k16.row.col.f32.bf16.bf16.f32 " \
        "{%0,%1,%2,%3}, {%4,%5,%6,%7}, {%8,%9}, {%0,%1,%2,%3};" \
        : "+f"((d)[0]), "+f"((d)[1]), "+f"((d)[2]), "+f"((d)[3]) \
        : "r"((a)[0]), "r"((a)[1]), "r"((a)[2]), "r"((a)[3]), "r"(b0), "r"(b1))

// ---------------- prep: split x into bf16 hi|lo ----------------
__global__ __launch_bounds__(256) void convert_x(const float4* __restrict__ x4) {
    int idx = blockIdx.x * blockDim.x + threadIdx.x;     // MM*DD/4 = 2097152
    int m  = idx >> 6;
    int k4 = (idx & 63) << 2;
    float4 v = x4[idx];
    __nv_bfloat162 h01 = __floats2bfloat162_rn(v.x, v.y);
    __nv_bfloat162 h23 = __floats2bfloat162_rn(v.z, v.w);
    float lx = v.x - __low2float(h01);
    float ly = v.y - __high2float(h01);
    float lz = v.z - __low2float(h23);
    float lw = v.w - __high2float(h23);
    __nv_bfloat162 l01 = __floats2bfloat162_rn(lx, ly);
    __nv_bfloat162 l23 = __floats2bfloat162_rn(lz, lw);
    __nv_bfloat162* dh = reinterpret_cast<__nv_bfloat162*>(g_A2 + (size_t)m * K2 + k4);
    dh[0] = h01; dh[1] = h23;
    __nv_bfloat162* dl = reinterpret_cast<__nv_bfloat162*>(g_A2 + (size_t)m * K2 + DD + k4);
    dl[0] = l01; dl[1] = l23;
}

// ---------------- prep: split + transpose W ----------------
__global__ __launch_bounds__(256) void convert_w(const float* __restrict__ W) {
    int idx = blockIdx.x * blockDim.x + threadIdx.x;     // 131072
    int n = idx & (UU - 1);
    int k = idx >> 9;
    float w = W[(size_t)k * UU + n];
    __nv_bfloat16 h = __float2bfloat16(w);
    float l = w - __bfloat162float(h);
    g_B2t[(size_t)n * K2 + k]      = h;
    g_B2t[(size_t)n * K2 + DD + k] = __float2bfloat16(l);
}

// ---------------- GEMM via mma.sync ----------------
// CTA 128(M) x 128(N), K-chunk 32, double-buffered cp.async, 8 warps (warp tile 32x64).
// Inner MMA order: nt x mt innermost -> 16 independent accumulators, no HMMA RAW chains.
// B fragments loaded as x4 over nt-pairs; B regs reused for the lo term.
#define ROWB     80
#define BUF_SZ   (128 * ROWB)          // 10240 B
#define STAGE_SZ (4 * BUF_SZ)          // Ahi, Alo, Bhi, Blo = 40960 B
#define SM_TOTAL (2 * STAGE_SZ)        // 81920 B

__device__ __forceinline__ void load_chunk(uint32_t stage_base, int bm, int bn, int k0, int tid) {
    const char* gA = reinterpret_cast<const char*>(g_A2);
    const char* gB = reinterpret_cast<const char*>(g_B2t);
#pragma unroll
    for (int r = 0; r < 2; r++) {
        int idx = tid + r * 256;          // 0..511
        int row = idx >> 2;
        int seg = (idx & 3) << 4;         // 0,16,32,48
        uint32_t so = stage_base + row * ROWB + seg;
        const char* srcA = gA + (size_t)(bm + row) * 1024 + k0 * 2 + seg;
        const char* srcB = gB + (size_t)(bn + row) * 1024 + k0 * 2 + seg;
        CP16(so,              srcA);        // A hi
        CP16(so + BUF_SZ,     srcA + 512);  // A lo
        CP16(so + 2 * BUF_SZ, srcB);        // B hi
        CP16(so + 3 * BUF_SZ, srcB + 512);  // B lo
    }
}

__global__ __launch_bounds__(256, 2) void indrnn_gemm_mma(
    const float* __restrict__ bias, float* __restrict__ C)
{
    extern __shared__ char smem[];
    const uint32_t sbase = smem_u32(smem);
    const int tid  = threadIdx.x;
    const int wid  = tid >> 5;
    const int lane = tid & 31;
    const int bm   = blockIdx.y * 128;
    const int bn   = blockIdx.x * 128;
    const int wm   = (wid & 3) * 32;
    const int wn   = (wid >> 2) * 64;

    float acc[2][8][4];
#pragma unroll
    for (int mt = 0; mt < 2; mt++)
#pragma unroll
        for (int nt = 0; nt < 8; nt++)
#pragma unroll
            for (int i = 0; i < 4; i++) acc[mt][nt][i] = 0.0f;

    load_chunk(sbase,            bm, bn, 0,  tid); CP_COMMIT();
    load_chunk(sbase + STAGE_SZ, bm, bn, 32, tid); CP_COMMIT();

    // per-lane ldmatrix base offsets
    // A x4: lanes 0-15 -> rows of 16x16 tile, lanes 16-31 -> +16B col half
    const uint32_t a_base = (wm + (lane & 15)) * ROWB + (lane >> 4) * 16;
    // B x4 over nt-pair: lane>>4 selects nt within pair, (lane>>3)&1 selects k-half
    const uint32_t b_base = (wn + ((lane >> 4) & 1) * 8 + (lane & 7)) * ROWB
                          + ((lane >> 3) & 1) * 16;

    for (int c = 0; c < 8; c++) {
        if (c < 7) { CP_WAITN(1); } else { CP_WAITN(0); }
        __syncthreads();

        const uint32_t st  = sbase + (c & 1) * STAGE_SZ;
        const uint32_t aHi = st;
        const uint32_t aLo = st + BUF_SZ;
        const uint32_t bHi = st + 2 * BUF_SZ;
        const uint32_t bLo = st + 3 * BUF_SZ;

#pragma unroll
        for (int k16 = 0; k16 < 2; k16++) {
            const uint32_t kb = k16 * 32;
            uint32_t ah[2][4], al[2][4], bf[8][2];
#pragma unroll
            for (int mt = 0; mt < 2; mt++) {
                LDSM_X4(ah[mt][0], ah[mt][1], ah[mt][2], ah[mt][3],
                        aHi + a_base + mt * (16 * ROWB) + kb);
                LDSM_X4(al[mt][0], al[mt][1], al[mt][2], al[mt][3],
                        aLo + a_base + mt * (16 * ROWB) + kb);
            }
#pragma unroll
            for (int np = 0; np < 4; np++)
                LDSM_X4(bf[2 * np][0], bf[2 * np][1], bf[2 * np + 1][0], bf[2 * np + 1][1],
                        bHi + b_base + np * (16 * ROWB) + kb);

            // term 1: hi*hi  (16 independent accumulators back-to-back)
#pragma unroll
            for (int nt = 0; nt < 8; nt++) {
                MMA_BF16(acc[0][nt], ah[0], bf[nt][0], bf[nt][1]);
                MMA_BF16(acc[1][nt], ah[1], bf[nt][0], bf[nt][1]);
            }
            // term 2: lo*hi
#pragma unroll
            for (int nt = 0; nt < 8; nt++) {
                MMA_BF16(acc[0][nt], al[0], bf[nt][0], bf[nt][1]);
                MMA_BF16(acc[1][nt], al[1], bf[nt][0], bf[nt][1]);
            }
            // reload B regs with lo half, term 3: hi*lo
#pragma unroll
            for (int np = 0; np < 4; np++)
                LDSM_X4(bf[2 * np][0], bf[2 * np][1], bf[2 * np + 1][0], bf[2 * np + 1][1],
                        bLo + b_base + np * (16 * ROWB) + kb);
#pragma unroll
            for (int nt = 0; nt < 8; nt++) {
                MMA_BF16(acc[0][nt], ah[0], bf[nt][0], bf[nt][1]);
                MMA_BF16(acc[1][nt], ah[1], bf[nt][0], bf[nt][1]);
            }
        }

        __syncthreads();
        if (c + 2 < 8) { load_chunk(st, bm, bn, (c + 2) * 32, tid); CP_COMMIT(); }
    }

    // epilogue
    const int m0   = bm + wm + (lane >> 2);
    const int col0 = bn + wn + (lane & 3) * 2;
#pragma unroll
    for (int mt = 0; mt < 2; mt++) {
#pragma unroll
        for (int nt = 0; nt < 8; nt++) {
            const int r = m0 + mt * 16;
            const int cc = col0 + nt * 8;
            const float2 bv = *reinterpret_cast<const float2*>(bias + cc);
            float2 o0, o1;
            o0.x = acc[mt][nt][0] + bv.x;
            o0.y = acc[mt][nt][1] + bv.y;
            o1.x = acc[mt][nt][2] + bv.x;
            o1.y = acc[mt][nt][3] + bv.y;
            *reinterpret_cast<float2*>(C + (size_t)r * UU + cc)       = o0;
            *reinterpret_cast<float2*>(C + (size_t)(r + 8) * UU + cc) = o1;
        }
    }
}

// ---------------- scan: cp.async smem ring (8 stages x 16 timesteps) ----------------
// Block = 128 lanes (one b, 128 consecutive u). Prefetch depth ~112 timesteps
// (~1200+ cyc) >> DRAM latency; register-free pipeline. 64 KB dynamic smem.
#define SC_TS    16
#define SC_NS    8
#define SC_STAGE (SC_TS * 128 * 4)          // 8192 B
#define SC_SMEM  (SC_NS * SC_STAGE)         // 65536 B

__device__ __forceinline__ void scan_issue_stage(uint32_t sm_stage, const char* gbase,
                                                 int t0, int tid) {
#pragma unroll
    for (int k = 0; k < 4; k++) {
        int j = tid + k * 128;              // 0..511
        int t = j >> 5;
        int seg = (j & 31) << 4;            // 16B chunks across 512B row
        CP16(sm_stage + t * 512 + seg, gbase + (size_t)(t0 + t) * (UU * 4) + seg);
    }
}

__global__ __launch_bounds__(128) void indrnn_scan(
    const float* __restrict__ h0,
    const float* __restrict__ u,
    float* __restrict__ out)
{
    extern __shared__ float sbuf[];
    const uint32_t sm = smem_u32(sbuf);
    const int tid = threadIdx.x;
    const int u0  = (blockIdx.x & 3) * 128;
    const int bb  = blockIdx.x >> 2;
    const int uu  = u0 + tid;

    const float uc = fminf(fmaxf(u[uu], 0.0f), 1.0f);
    float h = h0[bb * UU + uu];

    float* pout = out + (size_t)bb * TT * UU + uu;               // store stream
    const char* gbase = reinterpret_cast<const char*>(out)
                      + ((size_t)bb * TT * UU + u0) * 4;         // load stream base

    // prologue: stages for t-blocks 0..6
#pragma unroll
    for (int s = 0; s < SC_NS - 1; s++) {
        scan_issue_stage(sm + s * SC_STAGE, gbase, s * SC_TS, tid);
        CP_COMMIT();
    }

#pragma unroll 1
    for (int blk = 0; blk < TT / SC_TS; blk++) {
        CP_WAITN(SC_NS - 2);
        __syncthreads();

        // issue next stage into the slot freed last iteration
        const int nb = blk + SC_NS - 1;
        if (nb < TT / SC_TS) {
            scan_issue_stage(sm + (nb & (SC_NS - 1)) * SC_STAGE, gbase, nb * SC_TS, tid);
        }
        CP_COMMIT();   // keep group count in lockstep with blk

        const float* stage = sbuf + (blk & (SC_NS - 1)) * (SC_TS * 128) + tid;
        const int t0 = blk * SC_TS;
#pragma unroll
        for (int i = 0; i < SC_TS; i++) {
            h = fmaxf(fmaf(h, uc, stage[i * 128]), 0.0f);
            pout[(size_t)(t0 + i) * UU] = h;
        }
    }
}

extern "C" void kernel_launch(void* const* d_in, const int* in_sizes, int n_in,
                              void* d_out, int out_size)
{
    const float* x  = (const float*)d_in[0];
    const float* h0 = (const float*)d_in[1];
    const float* W  = (const float*)d_in[2];
    const float* u  = (const float*)d_in[3];
    const float* b  = (const float*)d_in[4];
    float* out = (float*)d_out;

    cudaFuncSetAttribute(indrnn_gemm_mma, cudaFuncAttributeMaxDynamicSharedMemorySize, SM_TOTAL);
    cudaFuncSetAttribute(indrnn_scan,     cudaFuncAttributeMaxDynamicSharedMemorySize, SC_SMEM);

    convert_x<<<(MM * DD / 4) / 256, 256>>>(reinterpret_cast<const float4*>(x));
    convert_w<<<(DD * UU) / 256, 256>>>(W);

    dim3 grid(UU / 128, MM / 128);   // (4, 256)
    indrnn_gemm_mma<<<grid, 256, SM_TOTAL>>>(b, out);

    indrnn_scan<<<(BATCH * UU) / 128, 128, SC_SMEM>>>(h0, u, out);
}